// round 15
// baseline (speedup 1.0000x reference)
#include <cuda_runtime.h>
#include <cuda_fp16.h>
#include <cstdint>

#define BATCH 4
#define SEQ   4096
#define EMB   1024
#define HD    64
#define NSEG  4
#define CH    1024

__device__ __half g_Qh[BATCH * SEQ * HD];     // fp16 (Q scale folded into W)
__device__ __half g_Kh[BATCH * SEQ * HD];     // fp16
__device__ __half g_Vh[BATCH * HD * SEQ];     // V transposed [b][d][s], fp16
__device__ __half g_Wh[192 * EMB];            // stacked Wq(scaled)|Wk|Wv, fp16
__device__ float  g_pO[BATCH * NSEG * SEQ * HD];
__device__ float  g_pL[BATCH * NSEG * SEQ];

__device__ __forceinline__ float ex2(float x) {
    float r; asm("ex2.approx.f32 %0, %1;" : "=f"(r) : "f"(x)); return r;
}
__device__ __forceinline__ void mma_f16(float (&c)[4], uint32_t a0, uint32_t a1,
                                        uint32_t a2, uint32_t a3, uint32_t b0, uint32_t b1) {
    asm volatile(
        "mma.sync.aligned.m16n8k16.row.col.f32.f16.f16.f32 "
        "{%0,%1,%2,%3}, {%4,%5,%6,%7}, {%8,%9}, {%0,%1,%2,%3};"
        : "+f"(c[0]), "+f"(c[1]), "+f"(c[2]), "+f"(c[3])
        : "r"(a0), "r"(a1), "r"(a2), "r"(a3), "r"(b0), "r"(b1));
}
__device__ __forceinline__ void cp16(uint32_t s_addr, const void* g_ptr) {
    asm volatile("cp.async.cg.shared.global [%0], [%1], 16;\n" :: "r"(s_addr), "l"(g_ptr));
}
__device__ __forceinline__ uint32_t pack2(float a, float b) {
    __half2 h = __floats2half2_rn(a, b);
    return *(uint32_t*)&h;
}
__device__ __forceinline__ void ldsm4(uint32_t& r0, uint32_t& r1, uint32_t& r2,
                                      uint32_t& r3, const __half* p) {
    uint32_t addr = (uint32_t)__cvta_generic_to_shared(p);
    asm volatile("ldmatrix.sync.aligned.m8n8.x4.shared.b16 {%0,%1,%2,%3}, [%4];"
                 : "=r"(r0), "=r"(r1), "=r"(r2), "=r"(r3) : "r"(addr));
}

// ---------------------------------------------------------------------------
// Prepass: stacked fp16 weights, Wq pre-scaled by 0.125*log2(e).
// ---------------------------------------------------------------------------
__global__ __launch_bounds__(256) void wconv_kernel(
    const float* __restrict__ Wq, const float* __restrict__ Wk,
    const float* __restrict__ Wv)
{
    int i = blockIdx.x * 256 + threadIdx.x;       // float4 index, 49152 total
    int row = i >> 8, c = i & 255;
    const float* W = (row < 64) ? (Wq + (size_t)row * EMB)
                    : (row < 128) ? (Wk + (size_t)(row - 64) * EMB)
                                  : (Wv + (size_t)(row - 128) * EMB);
    float s = (row < 64) ? 0.18033688011112042f : 1.0f;
    float4 v = ((const float4*)W)[c];
    uint2 u = make_uint2(pack2(v.x * s, v.y * s), pack2(v.z * s, v.w * s));
    *(uint2*)&g_Wh[(size_t)row * EMB + c * 4] = u;
}

// ---------------------------------------------------------------------------
// Fused QKV GEMM: BM=128, BN=192, BK=32. 512 thr = 16 warps (4m x 4n),
// 3-stage cp.async, ONE sync per k-tile. x fp32 smem, W fp16 smem + ldmatrix.
// ---------------------------------------------------------------------------
#define XS_BUF   (128 * 40)                       // floats per stage
#define WS_BUF   (192 * 40)                       // halves per stage
#define QKV_SMEM (3 * XS_BUF * 4 + 3 * WS_BUF * 2)

__global__ __launch_bounds__(512, 1) void qkv_fused_kernel(const float* __restrict__ x)
{
    extern __shared__ __align__(16) float smem[];
    float*  xs  = smem;                           // 3 x [128][40] fp32
    __half* wsm = (__half*)(smem + 3 * XS_BUF);   // 3 x [192][40] fp16

    int m0 = blockIdx.x * 128;
    int tid = threadIdx.x;
    int w = tid >> 5, lane = tid & 31, g = lane >> 2, t = lane & 3;
    int wm = w >> 2, wn = w & 3;
    int lq = lane >> 3, lr = lane & 7;            // ldmatrix addressing

    auto issue_tile = [&](int it, int bf) {
        int k0 = it * 32;
        float* xd = xs + bf * XS_BUF;
#pragma unroll
        for (int i = 0; i < 2; i++) {             // x: 128x32 = 1024 float4
            int u = tid + i * 512;
            int row = u >> 3, c4 = u & 7;
            cp16((uint32_t)__cvta_generic_to_shared(&xd[row * 40 + c4 * 4]),
                 &x[(size_t)(m0 + row) * EMB + k0 + c4 * 4]);
        }
        __half* wd = wsm + bf * WS_BUF;
#pragma unroll
        for (int i = 0; i < 2; i++) {             // W: 192x32 fp16 = 768 x 16B
            int u = tid + i * 512;
            if (u < 768) {
                int row = u >> 2, c16 = u & 3;
                cp16((uint32_t)__cvta_generic_to_shared(&wd[row * 40 + c16 * 8]),
                     &g_Wh[(size_t)row * EMB + k0 + c16 * 8]);
            }
        }
        asm volatile("cp.async.commit_group;\n" ::: "memory");
    };

    float acc[2][6][4];
#pragma unroll
    for (int mi = 0; mi < 2; mi++)
#pragma unroll
        for (int ni = 0; ni < 6; ni++)
#pragma unroll
            for (int j = 0; j < 4; j++) acc[mi][ni][j] = 0.f;

    const int NIT = EMB / 32;
    issue_tile(0, 0);
    issue_tile(1, 1);

    for (int it = 0; it < NIT; it++) {
        if (it + 1 < NIT) { asm volatile("cp.async.wait_group 1;\n" ::: "memory"); }
        else              { asm volatile("cp.async.wait_group 0;\n" ::: "memory"); }
        __syncthreads();
        if (it + 2 < NIT) issue_tile(it + 2, (it + 2) % 3);

        const float*  xb = xs + (it % 3) * XS_BUF;
        const __half* wb = wsm + (it % 3) * WS_BUF;

#pragma unroll
        for (int c = 0; c < 2; c++) {
            uint32_t a[2][4];
#pragma unroll
            for (int mi = 0; mi < 2; mi++) {
                int r = wm * 32 + mi * 16 + g;
                float2 f0 = *(const float2*)&xb[r * 40 + 16 * c + 2 * t];
                float2 f1 = *(const float2*)&xb[(r + 8) * 40 + 16 * c + 2 * t];
                float2 f2 = *(const float2*)&xb[r * 40 + 16 * c + 2 * t + 8];
                float2 f3 = *(const float2*)&xb[(r + 8) * 40 + 16 * c + 2 * t + 8];
                a[mi][0] = pack2(f0.x, f0.y);
                a[mi][1] = pack2(f1.x, f1.y);
                a[mi][2] = pack2(f2.x, f2.y);
                a[mi][3] = pack2(f3.x, f3.y);
            }
#pragma unroll
            for (int nip = 0; nip < 3; nip++) {   // ni pairs via ldmatrix.x4
                int ni = 2 * nip;
                uint32_t b0, b1, b2, b3;
                int d = (wn + 4 * (ni + (lq >> 1))) * 8 + lr;
                ldsm4(b0, b1, b2, b3, &wb[d * 40 + 16 * c + 8 * (lq & 1)]);
                mma_f16(acc[0][ni], a[0][0], a[0][1], a[0][2], a[0][3], b0, b1);
                mma_f16(acc[1][ni], a[1][0], a[1][1], a[1][2], a[1][3], b0, b1);
                mma_f16(acc[0][ni + 1], a[0][0], a[0][1], a[0][2], a[0][3], b2, b3);
                mma_f16(acc[1][ni + 1], a[1][0], a[1][1], a[1][2], a[1][3], b2, b3);
            }
        }
    }
    __syncthreads();                              // all warps done with smem

    // Epilogue: Q/K direct fp16 stores (scale already in W).
#pragma unroll
    for (int mi = 0; mi < 2; mi++)
#pragma unroll
        for (int ni = 0; ni < 4; ni++) {
            int gcol = (wn + 4 * ni) * 8 + 2 * t;
            int r = m0 + wm * 32 + mi * 16 + g;
            __half* O = (gcol < 64) ? g_Qh : g_Kh;
            int cc = gcol & 63;
            *(uint32_t*)&O[(size_t)r * HD + cc] = pack2(acc[mi][ni][0], acc[mi][ni][1]);
            *(uint32_t*)&O[(size_t)(r + 8) * HD + cc] = pack2(acc[mi][ni][2], acc[mi][ni][3]);
        }

    // V transpose through smem: hs[64 d][136]
    __half* hs = (__half*)smem;
#pragma unroll
    for (int mi = 0; mi < 2; mi++)
#pragma unroll
        for (int ni = 4; ni < 6; ni++) {
            int d = (wn + 4 * ni) * 8 + 2 * t - 128;
            int rl = wm * 32 + mi * 16 + g;
            hs[d * 136 + rl]           = __float2half_rn(acc[mi][ni][0]);
            hs[(d + 1) * 136 + rl]     = __float2half_rn(acc[mi][ni][1]);
            hs[d * 136 + rl + 8]       = __float2half_rn(acc[mi][ni][2]);
            hs[(d + 1) * 136 + rl + 8] = __float2half_rn(acc[mi][ni][3]);
        }
    __syncthreads();
    int b = m0 >> 12, s0 = m0 & (SEQ - 1);
#pragma unroll
    for (int i = 0; i < 2; i++) {
        int u = tid + i * 512;                    // 1024 uint4 = 64d x 16
        int d = u >> 4, c = u & 15;
        uint4 v = *(const uint4*)&hs[d * 136 + c * 8];
        *(uint4*)&g_Vh[((size_t)(b * HD + d)) * SEQ + s0 + c * 8] = v;
    }
}

// ---------------------------------------------------------------------------
// fp16 tensor-core split-K flash attention. Q-tile 64, 4 warps (r10-proven
// fragment code). 3-stage cp.async, ONE sync per k-tile, dynamic smem
// (64.5 KB -> up to 3 CTAs/SM).
// ---------------------------------------------------------------------------
#define KV_T      (64 * 72)                       // halves per K/V tile
#define ATTN_SMEM (7 * KV_T * 2)                  // q + 3k + 3v

__global__ __launch_bounds__(128) void attn_kernel()
{
    extern __shared__ __align__(16) __half sh[];
    __half* qs = sh;                              // [64][72]
    __half* ks = sh + KV_T;                       // 3 x [64][72]
    __half* vs = sh + 4 * KV_T;                   // 3 x [64][72]

    int qt = blockIdx.x, b = blockIdx.y, seg = blockIdx.z;
    int q0 = qt * 64, k0 = seg * CH;
    if (k0 >= q0 + 64) return;
    int kend = min(k0 + CH, q0 + 64);
    int nt = (kend - k0 + 63) >> 6;

    int tid = threadIdx.x, w = tid >> 5, lane = tid & 31, g = lane >> 2, t = lane & 3;
    const size_t base = (size_t)b * SEQ * HD;
    int lrow = tid >> 3, lc8 = tid & 7;
    int lq = lane >> 3, lr = lane & 7;
    int lmoff = ((lq >> 1) * 8 + lr) * 72 + 8 * (lq & 1);

#pragma unroll
    for (int i = 0; i < 4; i++) {
        int row = lrow + i * 16;
        *(uint4*)&qs[row * 72 + lc8 * 8] =
            *(const uint4*)&g_Qh[base + (size_t)(q0 + row) * HD + lc8 * 8];
    }
    __syncthreads();
    uint32_t qa[4][4];
    {
        int r = w * 16 + g;
#pragma unroll
        for (int c = 0; c < 4; c++) {
            qa[c][0] = *(const uint32_t*)&qs[r * 72 + 2 * t + 16 * c];
            qa[c][1] = *(const uint32_t*)&qs[(r + 8) * 72 + 2 * t + 16 * c];
            qa[c][2] = *(const uint32_t*)&qs[r * 72 + 2 * t + 8 + 16 * c];
            qa[c][3] = *(const uint32_t*)&qs[(r + 8) * 72 + 2 * t + 8 + 16 * c];
        }
    }

    float oacc[8][4];
#pragma unroll
    for (int nd = 0; nd < 8; nd++)
#pragma unroll
        for (int j = 0; j < 4; j++) oacc[nd][j] = 0.f;
    float l0 = 0.f, l1 = 0.f;
    int r0 = q0 + w * 16 + g, r1 = r0 + 8;

    auto issue = [&](int kb, int bf) {
#pragma unroll
        for (int i = 0; i < 4; i++) {
            int row = lrow + i * 16;
            cp16((uint32_t)__cvta_generic_to_shared(&ks[bf * KV_T + row * 72 + lc8 * 8]),
                 &g_Kh[base + (size_t)(kb + row) * HD + lc8 * 8]);
            cp16((uint32_t)__cvta_generic_to_shared(&vs[bf * KV_T + row * 72 + lc8 * 8]),
                 &g_Vh[((size_t)(b * HD + row)) * SEQ + kb + lc8 * 8]);
        }
        asm volatile("cp.async.commit_group;\n" ::: "memory");
    };

    issue(k0, 0);
    if (nt > 1) issue(k0 + 64, 1);

    for (int kt = 0; kt < nt; kt++) {
        int kb = k0 + kt * 64;
        if (kt + 1 < nt) { asm volatile("cp.async.wait_group 1;\n" ::: "memory"); }
        else             { asm volatile("cp.async.wait_group 0;\n" ::: "memory"); }
        __syncthreads();
        if (kt + 2 < nt) issue(kb + 128, (kt + 2) % 3);

        const __half* kbuf = ks + (kt % 3) * KV_T;
        const __half* vbuf = vs + (kt % 3) * KV_T;

        float sacc[8][4];
#pragma unroll
        for (int n8 = 0; n8 < 8; n8++)
#pragma unroll
            for (int j = 0; j < 4; j++) sacc[n8][j] = 0.f;
#pragma unroll
        for (int c = 0; c < 4; c++)
#pragma unroll
            for (int np = 0; np < 4; np++) {      // n8 pairs via ldmatrix.x4
                uint32_t b0, b1, b2, b3;
                ldsm4(b0, b1, b2, b3, &kbuf[np * 16 * 72 + 16 * c + lmoff]);
                mma_f16(sacc[2 * np],     qa[c][0], qa[c][1], qa[c][2], qa[c][3], b0, b1);
                mma_f16(sacc[2 * np + 1], qa[c][0], qa[c][1], qa[c][2], qa[c][3], b2, b3);
            }

        uint32_t ph[8][2];
        if (kb + 63 <= q0 + w * 16) {             // fully below diagonal: no mask
#pragma unroll
            for (int n8 = 0; n8 < 8; n8++) {
                float p0 = ex2(sacc[n8][0]);
                float p1 = ex2(sacc[n8][1]);
                float p2 = ex2(sacc[n8][2]);
                float p3 = ex2(sacc[n8][3]);
                l0 += p0 + p1; l1 += p2 + p3;
                ph[n8][0] = pack2(p0, p1);
                ph[n8][1] = pack2(p2, p3);
            }
        } else {
#pragma unroll
            for (int n8 = 0; n8 < 8; n8++) {
                int c = kb + n8 * 8 + 2 * t;
                float p0 = (c     <= r0) ? ex2(sacc[n8][0]) : 0.f;
                float p1 = (c + 1 <= r0) ? ex2(sacc[n8][1]) : 0.f;
                float p2 = (c     <= r1) ? ex2(sacc[n8][2]) : 0.f;
                float p3 = (c + 1 <= r1) ? ex2(sacc[n8][3]) : 0.f;
                l0 += p0 + p1; l1 += p2 + p3;
                ph[n8][0] = pack2(p0, p1);
                ph[n8][1] = pack2(p2, p3);
            }
        }

#pragma unroll
        for (int c2 = 0; c2 < 4; c2++) {
            uint32_t a0 = ph[2 * c2][0], a1 = ph[2 * c2][1];
            uint32_t a2 = ph[2 * c2 + 1][0], a3 = ph[2 * c2 + 1][1];
#pragma unroll
            for (int dp = 0; dp < 4; dp++) {      // nd pairs via ldmatrix.x4
                uint32_t b0, b1, b2, b3;
                ldsm4(b0, b1, b2, b3, &vbuf[dp * 16 * 72 + 16 * c2 + lmoff]);
                mma_f16(oacc[2 * dp],     a0, a1, a2, a3, b0, b1);
                mma_f16(oacc[2 * dp + 1], a0, a1, a2, a3, b2, b3);
            }
        }
    }

    float* po = &g_pO[(size_t)(b * NSEG + seg) * SEQ * HD];
#pragma unroll
    for (int nd = 0; nd < 8; nd++) {
        int d = nd * 8 + 2 * t;
        *(float2*)&po[(size_t)r0 * HD + d] = make_float2(oacc[nd][0], oacc[nd][1]);
        *(float2*)&po[(size_t)r1 * HD + d] = make_float2(oacc[nd][2], oacc[nd][3]);
    }
    l0 += __shfl_xor_sync(0xffffffffu, l0, 1);
    l0 += __shfl_xor_sync(0xffffffffu, l0, 2);
    l1 += __shfl_xor_sync(0xffffffffu, l1, 1);
    l1 += __shfl_xor_sync(0xffffffffu, l1, 2);
    if (t == 0) {
        g_pL[(size_t)(b * NSEG + seg) * SEQ + r0] = l0;
        g_pL[(size_t)(b * NSEG + seg) * SEQ + r1] = l1;
    }
}

// ---------------------------------------------------------------------------
__global__ __launch_bounds__(256) void reduce_kernel(float* __restrict__ out)
{
    int idx = blockIdx.x * 256 + threadIdx.x;     // float4 units
    if (idx >= BATCH * SEQ * HD / 4) return;
    int d4  = idx & 15;
    int row = (idx >> 4) & (SEQ - 1);
    int b   = idx >> 16;
    int ns  = (row / CH) + 1;

    float4 s = make_float4(0.f, 0.f, 0.f, 0.f);
    float sl = 0.f;
    for (int g = 0; g < ns; g++) {
        float4 v = *(const float4*)&g_pO[((size_t)(b * NSEG + g) * SEQ + row) * HD + d4 * 4];
        s.x += v.x; s.y += v.y; s.z += v.z; s.w += v.w;
        sl += g_pL[(size_t)(b * NSEG + g) * SEQ + row];
    }
    float inv = __frcp_rn(sl);
    *(float4*)&out[((size_t)(b * SEQ) + row) * HD + d4 * 4] =
        make_float4(s.x * inv, s.y * inv, s.z * inv, s.w * inv);
}

// ---------------------------------------------------------------------------
extern "C" void kernel_launch(void* const* d_in, const int* in_sizes, int n_in,
                              void* d_out, int out_size)
{
    const float* x  = (const float*)d_in[0];
    const float* Wq = (const float*)d_in[1];
    const float* Wk = (const float*)d_in[2];
    const float* Wv = (const float*)d_in[3];
    float* out = (float*)d_out;

    cudaFuncSetAttribute(qkv_fused_kernel,
                         cudaFuncAttributeMaxDynamicSharedMemorySize, QKV_SMEM);
    cudaFuncSetAttribute(attn_kernel,
                         cudaFuncAttributeMaxDynamicSharedMemorySize, ATTN_SMEM);

    wconv_kernel<<<192, 256>>>(Wq, Wk, Wv);
    qkv_fused_kernel<<<BATCH * SEQ / 128, 512, QKV_SMEM>>>(x);
    attn_kernel<<<dim3(SEQ / 64, BATCH, NSEG), 128, ATTN_SMEM>>>();
    reduce_kernel<<<(BATCH * SEQ * HD / 4 + 255) / 256, 256>>>(out);
}

// round 16
// speedup vs baseline: 1.0869x; 1.0869x over previous
#include <cuda_runtime.h>
#include <cuda_fp16.h>
#include <cstdint>

#define BATCH 4
#define SEQ   4096
#define EMB   1024
#define HD    64
#define NSEG  4
#define CH    1024

__device__ __half g_Qh[BATCH * SEQ * HD];     // fp16 (Q scale folded into W)
__device__ __half g_Kh[BATCH * SEQ * HD];     // fp16
__device__ __half g_Vh[BATCH * HD * SEQ];     // V transposed [b][d][s], fp16
__device__ __half g_Wh[192 * EMB];            // stacked Wq(scaled)|Wk|Wv, fp16
__device__ float  g_pO[BATCH * NSEG * SEQ * HD];
__device__ float  g_pL[BATCH * NSEG * SEQ];

__device__ __forceinline__ float ex2(float x) {
    float r; asm("ex2.approx.f32 %0, %1;" : "=f"(r) : "f"(x)); return r;
}
__device__ __forceinline__ void mma_f16(float (&c)[4], uint32_t a0, uint32_t a1,
                                        uint32_t a2, uint32_t a3, uint32_t b0, uint32_t b1) {
    asm volatile(
        "mma.sync.aligned.m16n8k16.row.col.f32.f16.f16.f32 "
        "{%0,%1,%2,%3}, {%4,%5,%6,%7}, {%8,%9}, {%0,%1,%2,%3};"
        : "+f"(c[0]), "+f"(c[1]), "+f"(c[2]), "+f"(c[3])
        : "r"(a0), "r"(a1), "r"(a2), "r"(a3), "r"(b0), "r"(b1));
}
__device__ __forceinline__ void cp16(uint32_t s_addr, const void* g_ptr) {
    asm volatile("cp.async.cg.shared.global [%0], [%1], 16;\n" :: "r"(s_addr), "l"(g_ptr));
}
__device__ __forceinline__ uint32_t pack2(float a, float b) {
    __half2 h = __floats2half2_rn(a, b);
    return *(uint32_t*)&h;
}
__device__ __forceinline__ void ldsm4(uint32_t& r0, uint32_t& r1, uint32_t& r2,
                                      uint32_t& r3, const __half* p) {
    uint32_t addr = (uint32_t)__cvta_generic_to_shared(p);
    asm volatile("ldmatrix.sync.aligned.m8n8.x4.shared.b16 {%0,%1,%2,%3}, [%4];"
                 : "=r"(r0), "=r"(r1), "=r"(r2), "=r"(r3) : "r"(addr));
}

// ---------------------------------------------------------------------------
// Prepass: stacked fp16 weights, Wq pre-scaled by 0.125*log2(e).
// ---------------------------------------------------------------------------
__global__ __launch_bounds__(256) void wconv_kernel(
    const float* __restrict__ Wq, const float* __restrict__ Wk,
    const float* __restrict__ Wv)
{
    int i = blockIdx.x * 256 + threadIdx.x;       // float4 index, 49152 total
    int row = i >> 8, c = i & 255;
    const float* W = (row < 64) ? (Wq + (size_t)row * EMB)
                    : (row < 128) ? (Wk + (size_t)(row - 64) * EMB)
                                  : (Wv + (size_t)(row - 128) * EMB);
    float s = (row < 64) ? 0.18033688011112042f : 1.0f;
    float4 v = ((const float4*)W)[c];
    uint2 u = make_uint2(pack2(v.x * s, v.y * s), pack2(v.z * s, v.w * s));
    *(uint2*)&g_Wh[(size_t)row * EMB + c * 4] = u;
}

// ---------------------------------------------------------------------------
// Fused QKV GEMM: BM=128, BN=192, BK=32. 512 thr = 16 warps (4m x 4n),
// 2-stage cp.async. x fp32 smem, W fp16 smem + ldmatrix. (R10-proven)
// ---------------------------------------------------------------------------
#define XS_BUF   (128 * 40)                       // floats per stage
#define WS_BUF   (192 * 40)                       // halves per stage
#define QKV_SMEM (2 * XS_BUF * 4 + 2 * WS_BUF * 2)

__global__ __launch_bounds__(512, 1) void qkv_fused_kernel(const float* __restrict__ x)
{
    extern __shared__ __align__(16) float smem[];
    float*  xs  = smem;                           // 2 x [128][40] fp32
    __half* wsm = (__half*)(smem + 2 * XS_BUF);   // 2 x [192][40] fp16

    int m0 = blockIdx.x * 128;
    int tid = threadIdx.x;
    int w = tid >> 5, lane = tid & 31, g = lane >> 2, t = lane & 3;
    int wm = w >> 2, wn = w & 3;
    int lq = lane >> 3, lr = lane & 7;            // ldmatrix addressing

    auto issue_tile = [&](int it, int bf) {
        int k0 = it * 32;
        float* xd = xs + bf * XS_BUF;
#pragma unroll
        for (int i = 0; i < 2; i++) {             // x: 128x32 = 1024 float4
            int u = tid + i * 512;
            int row = u >> 3, c4 = u & 7;
            cp16((uint32_t)__cvta_generic_to_shared(&xd[row * 40 + c4 * 4]),
                 &x[(size_t)(m0 + row) * EMB + k0 + c4 * 4]);
        }
        __half* wd = wsm + bf * WS_BUF;
#pragma unroll
        for (int i = 0; i < 2; i++) {             // W: 192x32 fp16 = 768 x 16B
            int u = tid + i * 512;
            if (u < 768) {
                int row = u >> 2, c16 = u & 3;
                cp16((uint32_t)__cvta_generic_to_shared(&wd[row * 40 + c16 * 8]),
                     &g_Wh[(size_t)row * EMB + k0 + c16 * 8]);
            }
        }
        asm volatile("cp.async.commit_group;\n" ::: "memory");
    };

    float acc[2][6][4];
#pragma unroll
    for (int mi = 0; mi < 2; mi++)
#pragma unroll
        for (int ni = 0; ni < 6; ni++)
#pragma unroll
            for (int j = 0; j < 4; j++) acc[mi][ni][j] = 0.f;

    const int NIT = EMB / 32;
    issue_tile(0, 0);

    for (int it = 0; it < NIT; it++) {
        if (it + 1 < NIT) {
            issue_tile(it + 1, (it + 1) & 1);
            asm volatile("cp.async.wait_group 1;\n" ::: "memory");
        } else {
            asm volatile("cp.async.wait_group 0;\n" ::: "memory");
        }
        __syncthreads();

        const float*  xb = xs + (it & 1) * XS_BUF;
        const __half* wb = wsm + (it & 1) * WS_BUF;

#pragma unroll
        for (int c = 0; c < 2; c++) {
            uint32_t a[2][4];
#pragma unroll
            for (int mi = 0; mi < 2; mi++) {
                int r = wm * 32 + mi * 16 + g;
                float2 f0 = *(const float2*)&xb[r * 40 + 16 * c + 2 * t];
                float2 f1 = *(const float2*)&xb[(r + 8) * 40 + 16 * c + 2 * t];
                float2 f2 = *(const float2*)&xb[r * 40 + 16 * c + 2 * t + 8];
                float2 f3 = *(const float2*)&xb[(r + 8) * 40 + 16 * c + 2 * t + 8];
                a[mi][0] = pack2(f0.x, f0.y);
                a[mi][1] = pack2(f1.x, f1.y);
                a[mi][2] = pack2(f2.x, f2.y);
                a[mi][3] = pack2(f3.x, f3.y);
            }
#pragma unroll
            for (int nip = 0; nip < 3; nip++) {   // ni pairs via ldmatrix.x4
                int ni = 2 * nip;
                uint32_t b0, b1, b2, b3;
                int d = (wn + 4 * (ni + (lq >> 1))) * 8 + lr;
                ldsm4(b0, b1, b2, b3, &wb[d * 40 + 16 * c + 8 * (lq & 1)]);
                mma_f16(acc[0][ni], a[0][0], a[0][1], a[0][2], a[0][3], b0, b1);
                mma_f16(acc[1][ni], a[1][0], a[1][1], a[1][2], a[1][3], b0, b1);
                mma_f16(acc[0][ni + 1], a[0][0], a[0][1], a[0][2], a[0][3], b2, b3);
                mma_f16(acc[1][ni + 1], a[1][0], a[1][1], a[1][2], a[1][3], b2, b3);
            }
        }
        __syncthreads();
    }

    // Epilogue: Q/K direct fp16 stores (scale already in W).
#pragma unroll
    for (int mi = 0; mi < 2; mi++)
#pragma unroll
        for (int ni = 0; ni < 4; ni++) {
            int gcol = (wn + 4 * ni) * 8 + 2 * t;
            int r = m0 + wm * 32 + mi * 16 + g;
            __half* O = (gcol < 64) ? g_Qh : g_Kh;
            int cc = gcol & 63;
            *(uint32_t*)&O[(size_t)r * HD + cc] = pack2(acc[mi][ni][0], acc[mi][ni][1]);
            *(uint32_t*)&O[(size_t)(r + 8) * HD + cc] = pack2(acc[mi][ni][2], acc[mi][ni][3]);
        }

    // V transpose through smem: hs[64 d][136]
    __half* hs = (__half*)smem;
#pragma unroll
    for (int mi = 0; mi < 2; mi++)
#pragma unroll
        for (int ni = 4; ni < 6; ni++) {
            int d = (wn + 4 * ni) * 8 + 2 * t - 128;
            int rl = wm * 32 + mi * 16 + g;
            hs[d * 136 + rl]           = __float2half_rn(acc[mi][ni][0]);
            hs[(d + 1) * 136 + rl]     = __float2half_rn(acc[mi][ni][1]);
            hs[d * 136 + rl + 8]       = __float2half_rn(acc[mi][ni][2]);
            hs[(d + 1) * 136 + rl + 8] = __float2half_rn(acc[mi][ni][3]);
        }
    __syncthreads();
    int b = m0 >> 12, s0 = m0 & (SEQ - 1);
#pragma unroll
    for (int i = 0; i < 2; i++) {
        int u = tid + i * 512;                    // 1024 uint4 = 64d x 16
        int d = u >> 4, c = u & 15;
        uint4 v = *(const uint4*)&hs[d * 136 + c * 8];
        *(uint4*)&g_Vh[((size_t)(b * HD + d)) * SEQ + s0 + c * 8] = v;
    }
}

// ---------------------------------------------------------------------------
// fp16 tensor-core split-K flash attention (R10-proven: static smem, 2-stage,
// 4 CTAs/SM). Q-tile 64, 4 warps, ldmatrix B-fragments, diagonal fast path.
// ---------------------------------------------------------------------------
__global__ __launch_bounds__(128) void attn_kernel()
{
    __shared__ __align__(16) __half qs[64 * 72];
    __shared__ __align__(16) __half ks[2][64 * 72];
    __shared__ __align__(16) __half vs[2][64 * 72];

    int qt = blockIdx.x, b = blockIdx.y, seg = blockIdx.z;
    int q0 = qt * 64, k0 = seg * CH;
    if (k0 >= q0 + 64) return;
    int kend = min(k0 + CH, q0 + 64);
    int nt = (kend - k0 + 63) >> 6;

    int tid = threadIdx.x, w = tid >> 5, lane = tid & 31, g = lane >> 2, t = lane & 3;
    const size_t base = (size_t)b * SEQ * HD;
    int lrow = tid >> 3, lc8 = tid & 7;
    int lq = lane >> 3, lr = lane & 7;
    int lmoff = ((lq >> 1) * 8 + lr) * 72 + 8 * (lq & 1);

#pragma unroll
    for (int i = 0; i < 4; i++) {
        int row = lrow + i * 16;
        *(uint4*)&qs[row * 72 + lc8 * 8] =
            *(const uint4*)&g_Qh[base + (size_t)(q0 + row) * HD + lc8 * 8];
    }
    __syncthreads();
    uint32_t qa[4][4];
    {
        int r = w * 16 + g;
#pragma unroll
        for (int c = 0; c < 4; c++) {
            qa[c][0] = *(const uint32_t*)&qs[r * 72 + 2 * t + 16 * c];
            qa[c][1] = *(const uint32_t*)&qs[(r + 8) * 72 + 2 * t + 16 * c];
            qa[c][2] = *(const uint32_t*)&qs[r * 72 + 2 * t + 8 + 16 * c];
            qa[c][3] = *(const uint32_t*)&qs[(r + 8) * 72 + 2 * t + 8 + 16 * c];
        }
    }

    float oacc[8][4];
#pragma unroll
    for (int nd = 0; nd < 8; nd++)
#pragma unroll
        for (int j = 0; j < 4; j++) oacc[nd][j] = 0.f;
    float l0 = 0.f, l1 = 0.f;
    int r0 = q0 + w * 16 + g, r1 = r0 + 8;

    auto issue = [&](int kb, int bf) {
#pragma unroll
        for (int i = 0; i < 4; i++) {
            int row = lrow + i * 16;
            cp16((uint32_t)__cvta_generic_to_shared(&ks[bf][row * 72 + lc8 * 8]),
                 &g_Kh[base + (size_t)(kb + row) * HD + lc8 * 8]);
            cp16((uint32_t)__cvta_generic_to_shared(&vs[bf][row * 72 + lc8 * 8]),
                 &g_Vh[((size_t)(b * HD + row)) * SEQ + kb + lc8 * 8]);
        }
        asm volatile("cp.async.commit_group;\n" ::: "memory");
    };

    issue(k0, 0);
    for (int kt = 0; kt < nt; kt++) {
        int kb = k0 + kt * 64;
        if (kt + 1 < nt) {
            issue(kb + 64, (kt + 1) & 1);
            asm volatile("cp.async.wait_group 1;\n" ::: "memory");
        } else {
            asm volatile("cp.async.wait_group 0;\n" ::: "memory");
        }
        __syncthreads();

        const __half* kbuf = ks[kt & 1];
        const __half* vbuf = vs[kt & 1];

        float sacc[8][4];
#pragma unroll
        for (int n8 = 0; n8 < 8; n8++)
#pragma unroll
            for (int j = 0; j < 4; j++) sacc[n8][j] = 0.f;
#pragma unroll
        for (int c = 0; c < 4; c++)
#pragma unroll
            for (int np = 0; np < 4; np++) {      // n8 pairs via ldmatrix.x4
                uint32_t b0, b1, b2, b3;
                ldsm4(b0, b1, b2, b3, &kbuf[np * 16 * 72 + 16 * c + lmoff]);
                mma_f16(sacc[2 * np],     qa[c][0], qa[c][1], qa[c][2], qa[c][3], b0, b1);
                mma_f16(sacc[2 * np + 1], qa[c][0], qa[c][1], qa[c][2], qa[c][3], b2, b3);
            }

        uint32_t ph[8][2];
        if (kb + 63 <= q0 + w * 16) {             // fully below diagonal: no mask
#pragma unroll
            for (int n8 = 0; n8 < 8; n8++) {
                float p0 = ex2(sacc[n8][0]);
                float p1 = ex2(sacc[n8][1]);
                float p2 = ex2(sacc[n8][2]);
                float p3 = ex2(sacc[n8][3]);
                l0 += p0 + p1; l1 += p2 + p3;
                ph[n8][0] = pack2(p0, p1);
                ph[n8][1] = pack2(p2, p3);
            }
        } else {
#pragma unroll
            for (int n8 = 0; n8 < 8; n8++) {
                int c = kb + n8 * 8 + 2 * t;
                float p0 = (c     <= r0) ? ex2(sacc[n8][0]) : 0.f;
                float p1 = (c + 1 <= r0) ? ex2(sacc[n8][1]) : 0.f;
                float p2 = (c     <= r1) ? ex2(sacc[n8][2]) : 0.f;
                float p3 = (c + 1 <= r1) ? ex2(sacc[n8][3]) : 0.f;
                l0 += p0 + p1; l1 += p2 + p3;
                ph[n8][0] = pack2(p0, p1);
                ph[n8][1] = pack2(p2, p3);
            }
        }

#pragma unroll
        for (int c2 = 0; c2 < 4; c2++) {
            uint32_t a0 = ph[2 * c2][0], a1 = ph[2 * c2][1];
            uint32_t a2 = ph[2 * c2 + 1][0], a3 = ph[2 * c2 + 1][1];
#pragma unroll
            for (int dp = 0; dp < 4; dp++) {      // nd pairs via ldmatrix.x4
                uint32_t b0, b1, b2, b3;
                ldsm4(b0, b1, b2, b3, &vbuf[dp * 16 * 72 + 16 * c2 + lmoff]);
                mma_f16(oacc[2 * dp],     a0, a1, a2, a3, b0, b1);
                mma_f16(oacc[2 * dp + 1], a0, a1, a2, a3, b2, b3);
            }
        }
        __syncthreads();
    }

    float* po = &g_pO[(size_t)(b * NSEG + seg) * SEQ * HD];
#pragma unroll
    for (int nd = 0; nd < 8; nd++) {
        int d = nd * 8 + 2 * t;
        *(float2*)&po[(size_t)r0 * HD + d] = make_float2(oacc[nd][0], oacc[nd][1]);
        *(float2*)&po[(size_t)r1 * HD + d] = make_float2(oacc[nd][2], oacc[nd][3]);
    }
    l0 += __shfl_xor_sync(0xffffffffu, l0, 1);
    l0 += __shfl_xor_sync(0xffffffffu, l0, 2);
    l1 += __shfl_xor_sync(0xffffffffu, l1, 1);
    l1 += __shfl_xor_sync(0xffffffffu, l1, 2);
    if (t == 0) {
        g_pL[(size_t)(b * NSEG + seg) * SEQ + r0] = l0;
        g_pL[(size_t)(b * NSEG + seg) * SEQ + r1] = l1;
    }
}

// ---------------------------------------------------------------------------
// Reduce: float4 + branchless MLP-8 (all segment loads issued up-front;
// invalid segments read a clamped valid address and are zero-masked).
// ---------------------------------------------------------------------------
__global__ __launch_bounds__(256) void reduce_kernel(float* __restrict__ out)
{
    int idx = blockIdx.x * 256 + threadIdx.x;     // float4 units
    if (idx >= BATCH * SEQ * HD / 4) return;
    int d4  = idx & 15;
    int row = (idx >> 4) & (SEQ - 1);
    int b   = idx >> 16;
    int ns  = (row / CH) + 1;

    float4 s = make_float4(0.f, 0.f, 0.f, 0.f);
    float sl = 0.f;
#pragma unroll
    for (int g = 0; g < NSEG; g++) {
        int gi = min(g, ns - 1);                  // clamped: always valid memory
        float m = (g < ns) ? 1.f : 0.f;
        float4 v = *(const float4*)&g_pO[((size_t)(b * NSEG + gi) * SEQ + row) * HD + d4 * 4];
        float lv = g_pL[(size_t)(b * NSEG + gi) * SEQ + row];
        s.x += m * v.x; s.y += m * v.y; s.z += m * v.z; s.w += m * v.w;
        sl += m * lv;
    }
    float inv = __frcp_rn(sl);
    *(float4*)&out[((size_t)(b * SEQ) + row) * HD + d4 * 4] =
        make_float4(s.x * inv, s.y * inv, s.z * inv, s.w * inv);
}

// ---------------------------------------------------------------------------
extern "C" void kernel_launch(void* const* d_in, const int* in_sizes, int n_in,
                              void* d_out, int out_size)
{
    const float* x  = (const float*)d_in[0];
    const float* Wq = (const float*)d_in[1];
    const float* Wk = (const float*)d_in[2];
    const float* Wv = (const float*)d_in[3];
    float* out = (float*)d_out;

    cudaFuncSetAttribute(qkv_fused_kernel,
                         cudaFuncAttributeMaxDynamicSharedMemorySize, QKV_SMEM);

    wconv_kernel<<<192, 256>>>(Wq, Wk, Wv);
    qkv_fused_kernel<<<BATCH * SEQ / 128, 512, QKV_SMEM>>>(x);
    attn_kernel<<<dim3(SEQ / 64, BATCH, NSEG), 128>>>();
    reduce_kernel<<<(BATCH * SEQ * HD / 4 + 255) / 256, 256>>>(out);
}

// round 17
// speedup vs baseline: 1.1253x; 1.0353x over previous
#include <cuda_runtime.h>
#include <cuda_fp16.h>
#include <cstdint>

#define BATCH 4
#define SEQ   4096
#define EMB   1024
#define HD    64
#define NSEG  4
#define CH    1024

__device__ __half g_Qh[BATCH * SEQ * HD];     // fp16 (Q scale folded into W)
__device__ __half g_Kh[BATCH * SEQ * HD];     // fp16
__device__ __half g_Vh[BATCH * HD * SEQ];     // V transposed [b][d][s], fp16
__device__ __half g_Wh[192 * EMB];            // stacked Wq(scaled)|Wk|Wv, fp16
__device__ float  g_pO[BATCH * NSEG * SEQ * HD];
__device__ float  g_pL[BATCH * NSEG * SEQ];

__device__ __forceinline__ float ex2(float x) {
    float r; asm("ex2.approx.f32 %0, %1;" : "=f"(r) : "f"(x)); return r;
}
__device__ __forceinline__ void mma_f16(float (&c)[4], uint32_t a0, uint32_t a1,
                                        uint32_t a2, uint32_t a3, uint32_t b0, uint32_t b1) {
    asm volatile(
        "mma.sync.aligned.m16n8k16.row.col.f32.f16.f16.f32 "
        "{%0,%1,%2,%3}, {%4,%5,%6,%7}, {%8,%9}, {%0,%1,%2,%3};"
        : "+f"(c[0]), "+f"(c[1]), "+f"(c[2]), "+f"(c[3])
        : "r"(a0), "r"(a1), "r"(a2), "r"(a3), "r"(b0), "r"(b1));
}
__device__ __forceinline__ void cp16(uint32_t s_addr, const void* g_ptr) {
    asm volatile("cp.async.cg.shared.global [%0], [%1], 16;\n" :: "r"(s_addr), "l"(g_ptr));
}
__device__ __forceinline__ uint32_t pack2(float a, float b) {
    __half2 h = __floats2half2_rn(a, b);
    return *(uint32_t*)&h;
}
__device__ __forceinline__ void ldsm4(uint32_t& r0, uint32_t& r1, uint32_t& r2,
                                      uint32_t& r3, const __half* p) {
    uint32_t addr = (uint32_t)__cvta_generic_to_shared(p);
    asm volatile("ldmatrix.sync.aligned.m8n8.x4.shared.b16 {%0,%1,%2,%3}, [%4];"
                 : "=r"(r0), "=r"(r1), "=r"(r2), "=r"(r3) : "r"(addr));
}

// ---------------------------------------------------------------------------
// Prepass: stacked fp16 weights, Wq pre-scaled by 0.125*log2(e).
// ---------------------------------------------------------------------------
__global__ __launch_bounds__(256) void wconv_kernel(
    const float* __restrict__ Wq, const float* __restrict__ Wk,
    const float* __restrict__ Wv)
{
    int i = blockIdx.x * 256 + threadIdx.x;       // float4 index, 49152 total
    int row = i >> 8, c = i & 255;
    const float* W = (row < 64) ? (Wq + (size_t)row * EMB)
                    : (row < 128) ? (Wk + (size_t)(row - 64) * EMB)
                                  : (Wv + (size_t)(row - 128) * EMB);
    float s = (row < 64) ? 0.18033688011112042f : 1.0f;
    float4 v = ((const float4*)W)[c];
    uint2 u = make_uint2(pack2(v.x * s, v.y * s), pack2(v.z * s, v.w * s));
    *(uint2*)&g_Wh[(size_t)row * EMB + c * 4] = u;
}

// ---------------------------------------------------------------------------
// Fused QKV GEMM: BM=128, BN=192, BK=32. 512 thr = 16 warps (4m x 4n),
// 2-stage cp.async. x fp32 smem, W fp16 smem + ldmatrix. (R10-proven)
// ---------------------------------------------------------------------------
#define XS_BUF   (128 * 40)                       // floats per stage
#define WS_BUF   (192 * 40)                       // halves per stage
#define QKV_SMEM (2 * XS_BUF * 4 + 2 * WS_BUF * 2)

__global__ __launch_bounds__(512, 1) void qkv_fused_kernel(const float* __restrict__ x)
{
    extern __shared__ __align__(16) float smem[];
    float*  xs  = smem;                           // 2 x [128][40] fp32
    __half* wsm = (__half*)(smem + 2 * XS_BUF);   // 2 x [192][40] fp16

    int m0 = blockIdx.x * 128;
    int tid = threadIdx.x;
    int w = tid >> 5, lane = tid & 31, g = lane >> 2, t = lane & 3;
    int wm = w >> 2, wn = w & 3;
    int lq = lane >> 3, lr = lane & 7;            // ldmatrix addressing

    auto issue_tile = [&](int it, int bf) {
        int k0 = it * 32;
        float* xd = xs + bf * XS_BUF;
#pragma unroll
        for (int i = 0; i < 2; i++) {             // x: 128x32 = 1024 float4
            int u = tid + i * 512;
            int row = u >> 3, c4 = u & 7;
            cp16((uint32_t)__cvta_generic_to_shared(&xd[row * 40 + c4 * 4]),
                 &x[(size_t)(m0 + row) * EMB + k0 + c4 * 4]);
        }
        __half* wd = wsm + bf * WS_BUF;
#pragma unroll
        for (int i = 0; i < 2; i++) {             // W: 192x32 fp16 = 768 x 16B
            int u = tid + i * 512;
            if (u < 768) {
                int row = u >> 2, c16 = u & 3;
                cp16((uint32_t)__cvta_generic_to_shared(&wd[row * 40 + c16 * 8]),
                     &g_Wh[(size_t)row * EMB + k0 + c16 * 8]);
            }
        }
        asm volatile("cp.async.commit_group;\n" ::: "memory");
    };

    float acc[2][6][4];
#pragma unroll
    for (int mi = 0; mi < 2; mi++)
#pragma unroll
        for (int ni = 0; ni < 6; ni++)
#pragma unroll
            for (int j = 0; j < 4; j++) acc[mi][ni][j] = 0.f;

    const int NIT = EMB / 32;
    issue_tile(0, 0);

    for (int it = 0; it < NIT; it++) {
        if (it + 1 < NIT) {
            issue_tile(it + 1, (it + 1) & 1);
            asm volatile("cp.async.wait_group 1;\n" ::: "memory");
        } else {
            asm volatile("cp.async.wait_group 0;\n" ::: "memory");
        }
        __syncthreads();

        const float*  xb = xs + (it & 1) * XS_BUF;
        const __half* wb = wsm + (it & 1) * WS_BUF;

#pragma unroll
        for (int c = 0; c < 2; c++) {
            uint32_t a[2][4];
#pragma unroll
            for (int mi = 0; mi < 2; mi++) {
                int r = wm * 32 + mi * 16 + g;
                float2 f0 = *(const float2*)&xb[r * 40 + 16 * c + 2 * t];
                float2 f1 = *(const float2*)&xb[(r + 8) * 40 + 16 * c + 2 * t];
                float2 f2 = *(const float2*)&xb[r * 40 + 16 * c + 2 * t + 8];
                float2 f3 = *(const float2*)&xb[(r + 8) * 40 + 16 * c + 2 * t + 8];
                a[mi][0] = pack2(f0.x, f0.y);
                a[mi][1] = pack2(f1.x, f1.y);
                a[mi][2] = pack2(f2.x, f2.y);
                a[mi][3] = pack2(f3.x, f3.y);
            }
#pragma unroll
            for (int nip = 0; nip < 3; nip++) {   // ni pairs via ldmatrix.x4
                int ni = 2 * nip;
                uint32_t b0, b1, b2, b3;
                int d = (wn + 4 * (ni + (lq >> 1))) * 8 + lr;
                ldsm4(b0, b1, b2, b3, &wb[d * 40 + 16 * c + 8 * (lq & 1)]);
                mma_f16(acc[0][ni], a[0][0], a[0][1], a[0][2], a[0][3], b0, b1);
                mma_f16(acc[1][ni], a[1][0], a[1][1], a[1][2], a[1][3], b0, b1);
                mma_f16(acc[0][ni + 1], a[0][0], a[0][1], a[0][2], a[0][3], b2, b3);
                mma_f16(acc[1][ni + 1], a[1][0], a[1][1], a[1][2], a[1][3], b2, b3);
            }
        }
        __syncthreads();
    }

    // Epilogue: Q/K direct fp16 stores (scale already in W).
#pragma unroll
    for (int mi = 0; mi < 2; mi++)
#pragma unroll
        for (int ni = 0; ni < 4; ni++) {
            int gcol = (wn + 4 * ni) * 8 + 2 * t;
            int r = m0 + wm * 32 + mi * 16 + g;
            __half* O = (gcol < 64) ? g_Qh : g_Kh;
            int cc = gcol & 63;
            *(uint32_t*)&O[(size_t)r * HD + cc] = pack2(acc[mi][ni][0], acc[mi][ni][1]);
            *(uint32_t*)&O[(size_t)(r + 8) * HD + cc] = pack2(acc[mi][ni][2], acc[mi][ni][3]);
        }

    // V transpose through smem: hs[64 d][136]
    __half* hs = (__half*)smem;
#pragma unroll
    for (int mi = 0; mi < 2; mi++)
#pragma unroll
        for (int ni = 4; ni < 6; ni++) {
            int d = (wn + 4 * ni) * 8 + 2 * t - 128;
            int rl = wm * 32 + mi * 16 + g;
            hs[d * 136 + rl]           = __float2half_rn(acc[mi][ni][0]);
            hs[(d + 1) * 136 + rl]     = __float2half_rn(acc[mi][ni][1]);
            hs[d * 136 + rl + 8]       = __float2half_rn(acc[mi][ni][2]);
            hs[(d + 1) * 136 + rl + 8] = __float2half_rn(acc[mi][ni][3]);
        }
    __syncthreads();
    int b = m0 >> 12, s0 = m0 & (SEQ - 1);
#pragma unroll
    for (int i = 0; i < 2; i++) {
        int u = tid + i * 512;                    // 1024 uint4 = 64d x 16
        int d = u >> 4, c = u & 15;
        uint4 v = *(const uint4*)&hs[d * 136 + c * 8];
        *(uint4*)&g_Vh[((size_t)(b * HD + d)) * SEQ + s0 + c * 8] = v;
    }
}

// ---------------------------------------------------------------------------
// fp16 flash attention: 3-stage cp.async, ONE sync/tile, XOR-swizzled 8KB
// tiles (no padding) -> 48KB static smem, 4 CTAs/SM. Q borrows ks[0].
// Swizzle: 16B chunk ch at row r stored at ch ^ (r&7).
// ---------------------------------------------------------------------------
__global__ __launch_bounds__(128) void attn_kernel()
{
    __shared__ __align__(16) __half ks[3][64 * 64];
    __shared__ __align__(16) __half vs[3][64 * 64];

    int qt = blockIdx.x, b = blockIdx.y, seg = blockIdx.z;
    int q0 = qt * 64, k0 = seg * CH;
    if (k0 >= q0 + 64) return;
    int kend = min(k0 + CH, q0 + 64);
    int nt = (kend - k0 + 63) >> 6;

    int tid = threadIdx.x, w = tid >> 5, lane = tid & 31, g = lane >> 2, t = lane & 3;
    const size_t base = (size_t)b * SEQ * HD;
    int lrow = tid >> 3, lc8 = tid & 7;           // loader: row group, chunk
    int lq = lane >> 3, lr = lane & 7;
    int lm_row = (lq >> 1) * 8 + lr;              // B-side ldmatrix row in 16-grp
    int swz_sel = lq & 1;

    // ---- Q into ks[0] (swizzled), extract fragments, then release buffer.
#pragma unroll
    for (int i = 0; i < 4; i++) {
        int row = lrow + i * 16;
        int ch = lc8 ^ (row & 7);
        cp16((uint32_t)__cvta_generic_to_shared(&ks[0][row * 64 + ch * 8]),
             &g_Qh[base + (size_t)(q0 + row) * HD + lc8 * 8]);
    }
    asm volatile("cp.async.commit_group;\ncp.async.wait_group 0;\n" ::: "memory");
    __syncthreads();
    uint32_t qa[4][4];
    {
        int r = w * 16 + g;                       // r&7 == g, (r+8)&7 == g
#pragma unroll
        for (int c = 0; c < 4; c++) {
            int chl = (2 * c) ^ g, chh = (2 * c + 1) ^ g;
            qa[c][0] = *(const uint32_t*)&ks[0][r * 64 + chl * 8 + 2 * t];
            qa[c][1] = *(const uint32_t*)&ks[0][(r + 8) * 64 + chl * 8 + 2 * t];
            qa[c][2] = *(const uint32_t*)&ks[0][r * 64 + chh * 8 + 2 * t];
            qa[c][3] = *(const uint32_t*)&ks[0][(r + 8) * 64 + chh * 8 + 2 * t];
        }
    }
    __syncthreads();                              // all extracted; ks[0] reusable

    float oacc[8][4];
#pragma unroll
    for (int nd = 0; nd < 8; nd++)
#pragma unroll
        for (int j = 0; j < 4; j++) oacc[nd][j] = 0.f;
    float l0 = 0.f, l1 = 0.f;
    int r0 = q0 + w * 16 + g, r1 = r0 + 8;

    auto issue = [&](int kb, int bf) {
#pragma unroll
        for (int i = 0; i < 4; i++) {
            int row = lrow + i * 16;
            int ch = lc8 ^ (row & 7);
            cp16((uint32_t)__cvta_generic_to_shared(&ks[bf][row * 64 + ch * 8]),
                 &g_Kh[base + (size_t)(kb + row) * HD + lc8 * 8]);
            cp16((uint32_t)__cvta_generic_to_shared(&vs[bf][row * 64 + ch * 8]),
                 &g_Vh[((size_t)(b * HD + row)) * SEQ + kb + lc8 * 8]);
        }
        asm volatile("cp.async.commit_group;\n" ::: "memory");
    };

    issue(k0, 0);
    if (nt > 1) issue(k0 + 64, 1);

    for (int kt = 0; kt < nt; kt++) {
        int kb = k0 + kt * 64;
        if (kt + 1 < nt) { asm volatile("cp.async.wait_group 1;\n" ::: "memory"); }
        else             { asm volatile("cp.async.wait_group 0;\n" ::: "memory"); }
        __syncthreads();
        if (kt + 2 < nt) issue(kb + 128, (kt + 2) % 3);

        const __half* kbuf = ks[kt % 3];
        const __half* vbuf = vs[kt % 3];

        float sacc[8][4];
#pragma unroll
        for (int n8 = 0; n8 < 8; n8++)
#pragma unroll
            for (int j = 0; j < 4; j++) sacc[n8][j] = 0.f;
#pragma unroll
        for (int c = 0; c < 4; c++) {
            int ch = ((2 * c + swz_sel) ^ lr) * 8;
#pragma unroll
            for (int np = 0; np < 4; np++) {      // n8 pairs via ldmatrix.x4
                uint32_t b0, b1, b2, b3;
                ldsm4(b0, b1, b2, b3, &kbuf[(np * 16 + lm_row) * 64 + ch]);
                mma_f16(sacc[2 * np],     qa[c][0], qa[c][1], qa[c][2], qa[c][3], b0, b1);
                mma_f16(sacc[2 * np + 1], qa[c][0], qa[c][1], qa[c][2], qa[c][3], b2, b3);
            }
        }

        uint32_t ph[8][2];
        if (kb + 63 <= q0 + w * 16) {             // fully below diagonal: no mask
#pragma unroll
            for (int n8 = 0; n8 < 8; n8++) {
                float p0 = ex2(sacc[n8][0]);
                float p1 = ex2(sacc[n8][1]);
                float p2 = ex2(sacc[n8][2]);
                float p3 = ex2(sacc[n8][3]);
                l0 += p0 + p1; l1 += p2 + p3;
                ph[n8][0] = pack2(p0, p1);
                ph[n8][1] = pack2(p2, p3);
            }
        } else {
#pragma unroll
            for (int n8 = 0; n8 < 8; n8++) {
                int c = kb + n8 * 8 + 2 * t;
                float p0 = (c     <= r0) ? ex2(sacc[n8][0]) : 0.f;
                float p1 = (c + 1 <= r0) ? ex2(sacc[n8][1]) : 0.f;
                float p2 = (c     <= r1) ? ex2(sacc[n8][2]) : 0.f;
                float p3 = (c + 1 <= r1) ? ex2(sacc[n8][3]) : 0.f;
                l0 += p0 + p1; l1 += p2 + p3;
                ph[n8][0] = pack2(p0, p1);
                ph[n8][1] = pack2(p2, p3);
            }
        }

#pragma unroll
        for (int c2 = 0; c2 < 4; c2++) {
            uint32_t a0 = ph[2 * c2][0], a1 = ph[2 * c2][1];
            uint32_t a2 = ph[2 * c2 + 1][0], a3 = ph[2 * c2 + 1][1];
            int ch = ((2 * c2 + swz_sel) ^ lr) * 8;
#pragma unroll
            for (int dp = 0; dp < 4; dp++) {      // nd pairs via ldmatrix.x4
                uint32_t b0, b1, b2, b3;
                ldsm4(b0, b1, b2, b3, &vbuf[(dp * 16 + lm_row) * 64 + ch]);
                mma_f16(oacc[2 * dp],     a0, a1, a2, a3, b0, b1);
                mma_f16(oacc[2 * dp + 1], a0, a1, a2, a3, b2, b3);
            }
        }
    }

    float* po = &g_pO[(size_t)(b * NSEG + seg) * SEQ * HD];
#pragma unroll
    for (int nd = 0; nd < 8; nd++) {
        int d = nd * 8 + 2 * t;
        *(float2*)&po[(size_t)r0 * HD + d] = make_float2(oacc[nd][0], oacc[nd][1]);
        *(float2*)&po[(size_t)r1 * HD + d] = make_float2(oacc[nd][2], oacc[nd][3]);
    }
    l0 += __shfl_xor_sync(0xffffffffu, l0, 1);
    l0 += __shfl_xor_sync(0xffffffffu, l0, 2);
    l1 += __shfl_xor_sync(0xffffffffu, l1, 1);
    l1 += __shfl_xor_sync(0xffffffffu, l1, 2);
    if (t == 0) {
        g_pL[(size_t)(b * NSEG + seg) * SEQ + r0] = l0;
        g_pL[(size_t)(b * NSEG + seg) * SEQ + r1] = l1;
    }
}

// ---------------------------------------------------------------------------
// Reduce: float4 + branchless MLP-8 (R16-proven).
// ---------------------------------------------------------------------------
__global__ __launch_bounds__(256) void reduce_kernel(float* __restrict__ out)
{
    int idx = blockIdx.x * 256 + threadIdx.x;     // float4 units
    if (idx >= BATCH * SEQ * HD / 4) return;
    int d4  = idx & 15;
    int row = (idx >> 4) & (SEQ - 1);
    int b   = idx >> 16;
    int ns  = (row / CH) + 1;

    float4 s = make_float4(0.f, 0.f, 0.f, 0.f);
    float sl = 0.f;
#pragma unroll
    for (int g = 0; g < NSEG; g++) {
        int gi = min(g, ns - 1);                  // clamped: always valid memory
        float m = (g < ns) ? 1.f : 0.f;
        float4 v = *(const float4*)&g_pO[((size_t)(b * NSEG + gi) * SEQ + row) * HD + d4 * 4];
        float lv = g_pL[(size_t)(b * NSEG + gi) * SEQ + row];
        s.x += m * v.x; s.y += m * v.y; s.z += m * v.z; s.w += m * v.w;
        sl += m * lv;
    }
    float inv = __frcp_rn(sl);
    *(float4*)&out[((size_t)(b * SEQ) + row) * HD + d4 * 4] =
        make_float4(s.x * inv, s.y * inv, s.z * inv, s.w * inv);
}

// ---------------------------------------------------------------------------
extern "C" void kernel_launch(void* const* d_in, const int* in_sizes, int n_in,
                              void* d_out, int out_size)
{
    const float* x  = (const float*)d_in[0];
    const float* Wq = (const float*)d_in[1];
    const float* Wk = (const float*)d_in[2];
    const float* Wv = (const float*)d_in[3];
    float* out = (float*)d_out;

    cudaFuncSetAttribute(qkv_fused_kernel,
                         cudaFuncAttributeMaxDynamicSharedMemorySize, QKV_SMEM);

    wconv_kernel<<<192, 256>>>(Wq, Wk, Wv);
    qkv_fused_kernel<<<BATCH * SEQ / 128, 512, QKV_SMEM>>>(x);
    attn_kernel<<<dim3(SEQ / 64, BATCH, NSEG), 128>>>();
    reduce_kernel<<<(BATCH * SEQ * HD / 4 + 255) / 256, 256>>>(out);
}